// round 3
// baseline (speedup 1.0000x reference)
#include <cuda_runtime.h>
#include <cstdint>

#define NMAPS   7
#define KPTS    768
#define WIDTH   1024
#define MAPPIX  (WIDTH * WIDTH)
#define KK      (KPTS * KPTS)                 // 589824
#define PLANE   ((size_t)NMAPS * KK)          // 4128768
#define RT_PER_MAP 192                         // 768 / 4 rows per block

// Interleaved PAF: g_pafi[m][y][x] = (PAF[m][0][y][x], PAF[m][1][y][x])
__device__ float2 g_pafi[NMAPS * MAPPIX];

__global__ void interleave_kernel(const float* __restrict__ paf) {
    int i = blockIdx.x * blockDim.x + threadIdx.x;
    if (i < NMAPS * MAPPIX) {
        int m = i >> 20;                 // / MAPPIX
        int p = i & (MAPPIX - 1);
        float a = paf[(size_t)(2 * m)     * MAPPIX + p];
        float b = paf[(size_t)(2 * m + 1) * MAPPIX + p];
        g_pafi[i] = make_float2(a, b);
    }
}

// Block = (map m, 4 consecutive p2 rows). 128 threads: thread t handles
// r = rt*4 + t/32, c = (t&31) + 32k for k in [0,24). Warp-coherent c => coalesced stores.
__global__ __launch_bounds__(128) void pair_kernel(const int* __restrict__ skel,
                                                   float* __restrict__ out) {
    int b  = blockIdx.x;
    int m  = b / RT_PER_MAP;
    int rt = b % RT_PER_MAP;
    int t  = threadIdx.x;

    __shared__ float4 p1tab[KPTS];   // {p1x, p1y, paf(p1).x, paf(p1).y}

    const float2* __restrict__ pafm = g_pafi + m * MAPPIX;

    for (int i = t; i < KPTS; i += 128) {
        int xi = skel[(m * KPTS + i) * 3 + 1];
        int yi = skel[(m * KPTS + i) * 3 + 2];
        float2 e = __ldg(&pafm[yi * WIDTH + xi]);
        p1tab[i] = make_float4((float)xi, (float)yi, e.x, e.y);
    }
    __syncthreads();

    int r  = rt * 4 + (t >> 5);
    int c0 = t & 31;

    int p2x = skel[((m + 1) * KPTS + r) * 3 + 1];
    int p2y = skel[((m + 1) * KPTS + r) * 3 + 2];
    float2 e2 = __ldg(&pafm[p2y * WIDTH + p2x]);
    float p2xf = (float)p2x, p2yf = (float)p2y;

    // pre[i] = p2 * ((i+1)/9) + 0.55 ;  sample x = i+1, i in [0,8)
    float prex[8], prey[8];
#pragma unroll
    for (int i = 0; i < 8; i++) {
        float cc = (float)((i + 1) / 9.0);
        prex[i] = fmaf(p2xf, cc, 0.55f);
        prey[i] = fmaf(p2yf, cc, 0.55f);
    }

    // floor trick yields (coord+1); fold the (+1,+1) into base: -(1*1024 + 1)
    const float2* __restrict__ pafm_adj = pafm - 1025;

    size_t base = (size_t)m * KK + (size_t)r * KPTS;
    float i2val = (float)((m + 1) * KPTS + r);

#pragma unroll 1
    for (int k = 0; k < 24; k++) {
        int c = c0 + 32 * k;
        float4 P = p1tab[c];
        // endpoint samples x=0 (p1) and x=9 (p2), exact
        float sx = P.z + e2.x;
        float sy = P.w + e2.y;
#pragma unroll
        for (int i = 0; i < 8; i++) {
            float C1 = (float)((8 - i) / 9.0);    // (9-x)/9
            float mx = fmaf(P.x, C1, prex[i]);    // ~ n_x/9 + 0.55
            float my = fmaf(P.y, C1, prey[i]);
            int lxb = __float_as_int(mx + 8388608.f) & 0x7FF;   // floor+1
            int lyb = __float_as_int(my + 8388608.f) & 0x7FF;
            float2 v = __ldg(&pafm_adj[lyb * WIDTH + lxb]);
            sx += v.x;
            sy += v.y;
        }
        float dx = p2xf - P.x;
        float dy = p2yf - P.y;
        float R2 = fmaf(dx, dx, dy * dy);
        float Rv = sqrtf(R2);
        float inv = (R2 > 0.f) ? (0.1f / Rv) : 0.f;   // NaN (R==0) -> 0
        float li = (dx * sx + dy * sy) * inv;

        size_t pos = base + c;
        out[pos]             = (float)(m * KPTS + c);  // i1
        out[PLANE + pos]     = i2val;                  // i2
        out[2 * PLANE + pos] = li;                     // cost
        out[3 * PLANE + pos] = Rv;                     // R
    }
}

extern "C" void kernel_launch(void* const* d_in, const int* in_sizes, int n_in,
                              void* d_out, int out_size) {
    const int*   skel;
    const float* paf;
    // skeletons = 6144*3 = 18432 elems; PAF = 7*2*1024*1024 = 14680064 elems
    if (in_sizes[0] < in_sizes[1]) {
        skel = (const int*)d_in[0];
        paf  = (const float*)d_in[1];
    } else {
        skel = (const int*)d_in[1];
        paf  = (const float*)d_in[0];
    }

    int total = NMAPS * MAPPIX;
    interleave_kernel<<<(total + 255) / 256, 256>>>(paf);
    pair_kernel<<<NMAPS * RT_PER_MAP, 128>>>(skel, (float*)d_out);
}

// round 4
// speedup vs baseline: 1.1191x; 1.1191x over previous
#include <cuda_runtime.h>
#include <cstdint>

#define NMAPS   7
#define KPTS    768
#define WIDTH   1024
#define MAPPIX  (WIDTH * WIDTH)
#define KK      (KPTS * KPTS)                 // 589824
#define PLANE   ((size_t)NMAPS * KK)          // 4128768
#define RT_PER_MAP 384                        // 768 / 2 rows per block

// Interleaved PAF: g_pafi[m][y][x] = (PAF[m][0][y][x], PAF[m][1][y][x])
__device__ float2 g_pafi[NMAPS * MAPPIX];
// Precomputed endpoint tables: {x, y, paf_m(p).x, paf_m(p).y}
__device__ float4 g_p1e[NMAPS * KPTS];   // segment m point i, sampled in map m
__device__ float4 g_p2e[NMAPS * KPTS];   // segment m+1 point i, sampled in map m

__global__ void interleave_kernel(const float* __restrict__ paf) {
    // 4 pixels per thread, float4 I/O
    int i = blockIdx.x * blockDim.x + threadIdx.x;   // quad index
    int nquads = NMAPS * MAPPIX / 4;
    if (i < nquads) {
        int m = i / (MAPPIX / 4);
        int q = i - m * (MAPPIX / 4);
        const float4* pa = (const float4*)(paf + (size_t)(2 * m)     * MAPPIX);
        const float4* pb = (const float4*)(paf + (size_t)(2 * m + 1) * MAPPIX);
        float4 a = __ldg(&pa[q]);
        float4 b = __ldg(&pb[q]);
        float4* dst = (float4*)(g_pafi + (size_t)m * MAPPIX + q * 4);
        dst[0] = make_float4(a.x, b.x, a.y, b.y);
        dst[1] = make_float4(a.z, b.z, a.w, b.w);
    }
}

__global__ void setup_kernel(const int* __restrict__ skel) {
    int i = blockIdx.x * blockDim.x + threadIdx.x;   // [0, NMAPS*KPTS)
    if (i < NMAPS * KPTS) {
        int m = i / KPTS;
        int p = i - m * KPTS;
        const float2* pafm = g_pafi + (size_t)m * MAPPIX;
        // p1: segment m
        int x1 = skel[(m * KPTS + p) * 3 + 1];
        int y1 = skel[(m * KPTS + p) * 3 + 2];
        float2 e1 = __ldg(&pafm[y1 * WIDTH + x1]);
        g_p1e[i] = make_float4((float)x1, (float)y1, e1.x, e1.y);
        // p2: segment m+1, sampled in map m
        int x2 = skel[((m + 1) * KPTS + p) * 3 + 1];
        int y2 = skel[((m + 1) * KPTS + p) * 3 + 2];
        float2 e2 = __ldg(&pafm[y2 * WIDTH + x2]);
        g_p2e[i] = make_float4((float)x2, (float)y2, e2.x, e2.y);
    }
}

// Block = (map m, 2 consecutive p2 rows). 128 threads: thread t handles
// r = rt*2 + t/64, c = (t&63) + 64k for k in [0,12). Warp-coherent c => coalesced stores.
__global__ __launch_bounds__(128) void pair_kernel(float* __restrict__ out) {
    int b  = blockIdx.x;
    int m  = b / RT_PER_MAP;
    int rt = b - m * RT_PER_MAP;
    int t  = threadIdx.x;

    int r  = rt * 2 + (t >> 6);
    int c0 = t & 63;

    const float4* __restrict__ p1tab = g_p1e + m * KPTS;
    float4 Q = __ldg(&g_p2e[m * KPTS + r]);
    float p2xf = Q.x, p2yf = Q.y;

    // pre[i] = p2 * ((i+1)/9) + 0.55 ;  interior sample x = i+1, i in [0,8)
    float prex[8], prey[8];
#pragma unroll
    for (int i = 0; i < 8; i++) {
        float cc = (float)((i + 1) / 9.0);
        prex[i] = fmaf(p2xf, cc, 0.55f);
        prey[i] = fmaf(p2yf, cc, 0.55f);
    }

    // floor trick yields (coord+1) in each dim; fold into base: -(1*1024 + 1)
    const float2* __restrict__ pafm_adj = g_pafi + (size_t)m * MAPPIX - 1025;

    size_t base = (size_t)m * KK + (size_t)r * KPTS;
    float i2val = (float)((m + 1) * KPTS + r);

#pragma unroll 1
    for (int k = 0; k < 12; k++) {
        int c = c0 + 64 * k;
        float4 P = __ldg(&p1tab[c]);
        // endpoint samples x=0 (p1) and x=9 (p2) are exact
        float sx = P.z + Q.z;
        float sy = P.w + Q.w;
#pragma unroll
        for (int i = 0; i < 8; i++) {
            float C1 = (float)((8 - i) / 9.0);    // (9-x)/9
            float mx = fmaf(P.x, C1, prex[i]);    // ~ n_x/9 + 0.55
            float my = fmaf(P.y, C1, prey[i]);
            int lxb = __float_as_int(mx + 8388608.f) & 0x7FF;   // floor+1
            int lyb = __float_as_int(my + 8388608.f) & 0x7FF;
            float2 v = __ldg(&pafm_adj[lyb * WIDTH + lxb]);
            sx += v.x;
            sy += v.y;
        }
        float dx = p2xf - P.x;
        float dy = p2yf - P.y;
        float R2 = fmaf(dx, dx, dy * dy);
        float Rv = sqrtf(R2);
        float inv = (R2 > 0.f) ? (0.1f / Rv) : 0.f;   // NaN (R==0) -> 0
        float li = (dx * sx + dy * sy) * inv;

        size_t pos = base + c;
        out[pos]             = (float)(m * KPTS + c);  // i1
        out[PLANE + pos]     = i2val;                  // i2
        out[2 * PLANE + pos] = li;                     // cost
        out[3 * PLANE + pos] = Rv;                     // R
    }
}

extern "C" void kernel_launch(void* const* d_in, const int* in_sizes, int n_in,
                              void* d_out, int out_size) {
    const int*   skel;
    const float* paf;
    // skeletons = 6144*3 = 18432 elems; PAF = 7*2*1024*1024 = 14680064 elems
    if (in_sizes[0] < in_sizes[1]) {
        skel = (const int*)d_in[0];
        paf  = (const float*)d_in[1];
    } else {
        skel = (const int*)d_in[1];
        paf  = (const float*)d_in[0];
    }

    int nquads = NMAPS * MAPPIX / 4;
    interleave_kernel<<<(nquads + 255) / 256, 256>>>(paf);
    setup_kernel<<<(NMAPS * KPTS + 255) / 256, 256>>>(skel);
    pair_kernel<<<NMAPS * RT_PER_MAP, 128>>>((float*)d_out);
}